// round 5
// baseline (speedup 1.0000x reference)
#include <cuda_runtime.h>
#include <math.h>

// Problem constants
#define RR 2048           // bs*NA
#define NEN 16
#define NALLY 15
#define HH 64
#define HDD 4
#define OD 256            // HH*HDD
#define FD 10             // END == ALD == 10
#define KK 650            // 64*10 + 10 bias lanes

// Scratch (static device globals -- no allocation allowed)
__device__ float g_W2p[KK*OD];       // ally W2 folded with pw1 (650x256)
__device__ float g_EmbEn[RR*OD];
__device__ float g_EmbAlSum[RR*OD];
__device__ float g_PassEmb[RR*3];

typedef unsigned long long ull;

__device__ __forceinline__ ull ffma2(ull a, ull b, ull c) {
    ull d;
    asm("fma.rn.f32x2 %0, %1, %2, %3;" : "=l"(d) : "l"(a), "l"(b), "l"(c));
    return d;
}
__device__ __forceinline__ ull pack2(float x, float y) {
    ull d;
    asm("mov.b64 %0, {%1, %2};" : "=l"(d) : "f"(x), "f"(y));
    return d;
}
__device__ __forceinline__ float2 unpack2(ull v) {
    float2 r;
    asm("mov.b64 {%0, %1}, %2;" : "=f"(r.x), "=f"(r.y) : "l"(v));
    return r;
}

// ---------------------------------------------------------------------------
// W2p[kk, hd*64+j] = sum_h W2full_al[kk, hd*64+h] * pw1[h*64+j]
// W2full_al rows: kk<640 -> ha_w2[k*2560 + i*256 + m]; kk>=640 -> ha_b2[(kk-640)*256+m]
__global__ void __launch_bounds__(256) w2p_kernel(const float* __restrict__ ha_w2,
                                                  const float* __restrict__ ha_b2,
                                                  const float* __restrict__ pw1) {
    __shared__ float wrow[256];
    const int kk = blockIdx.x;
    const int o  = threadIdx.x;
    float v;
    if (kk < 640) { int k = kk/10, i = kk - k*10; v = ha_w2[k*2560 + i*256 + o]; }
    else          { v = ha_b2[(kk-640)*256 + o]; }
    wrow[o] = v;
    __syncthreads();
    const int hd = o >> 6, j = o & 63;
    float s = 0.f;
#pragma unroll
    for (int h = 0; h < 64; h++) s = fmaf(wrow[hd*64 + h], __ldg(pw1 + h*64 + j), s);
    g_W2p[kk*256 + o] = s;
}

// ---------------------------------------------------------------------------
// Summed bilinear: per agent, row-sum the A-rows FIRST, then one [650]x[650,256].
// 16 agents per block ("rows" of the tile = agents). Grid = RR/16 = 128.
template<int NR, bool ENEMY>
__global__ void __launch_bounds__(128) summed_kernel(
    const float* __restrict__ feats,
    const float* __restrict__ W1, const float* __restrict__ B1,
    const float* __restrict__ W2, const float* __restrict__ B2, int strideK)
{
    __shared__ __align__(16) float a_sh[KK*16];   // [kk][agent]
    __shared__ float e_sh[16*161];                // [agent][rr*10+i], stride 161 (bank-spread)
    const int tid = threadIdx.x;
    const int ag0 = blockIdx.x * 16;

    // stage e for 16 agents (contiguous in gmem)
    for (int idx = tid; idx < 16*NR*FD; idx += 128) {
        int a = idx / (NR*FD), rem = idx - a*(NR*FD);
        e_sh[a*161 + rem] = feats[(ag0*NR)*FD + idx];
    }
    __syncthreads();

    // build a_sh: thread owns 8 (k, agent) pairs
#pragma unroll
    for (int p = 0; p < 8; p++) {
        int idx = tid + p*128;
        int a = idx & 15, k = idx >> 4;
        const float* ea = e_sh + a*161;
        float h[NR];
#pragma unroll
        for (int rr = 0; rr < NR; rr++) {
            float s = B1[k];
#pragma unroll
            for (int i = 0; i < FD; i++) s = fmaf(ea[rr*FD + i], __ldg(W1 + i*HH + k), s);
            h[rr] = fmaxf(s, 0.f);
        }
#pragma unroll
        for (int i = 0; i < FD; i++) {
            float s = 0.f;
#pragma unroll
            for (int rr = 0; rr < NR; rr++) s = fmaf(h[rr], ea[rr*FD + i], s);
            a_sh[(k*10 + i)*16 + a] = s;
        }
    }
    // bias rows: sum of e over entities
    for (int idx = tid; idx < 160; idx += 128) {
        int a = idx & 15, i = idx >> 4;
        const float* ea = e_sh + a*161;
        float s = 0.f;
#pragma unroll
        for (int rr = 0; rr < NR; rr++) s += ea[rr*FD + i];
        a_sh[(640 + i)*16 + a] = s;
    }
    __syncthreads();

    // main loop: identical shape to the per-row kernel; lanes = agents
    const int c0 = tid * 2;
    ull acc[8][2];
#pragma unroll
    for (int p = 0; p < 8; p++) { acc[p][0] = 0ull; acc[p][1] = 0ull; }

    for (int k = 0; k < 64; k++) {
        const float* wk = W2 + k*strideK + c0;
#pragma unroll
        for (int i = 0; i < 10; i++) {
            float2 wv = __ldg((const float2*)(wk + i*OD));
            ull w0 = pack2(wv.x, wv.x);
            ull w1d = pack2(wv.y, wv.y);
            const ulonglong2* ar = (const ulonglong2*)(a_sh + (k*10 + i)*16);
#pragma unroll
            for (int q = 0; q < 4; q++) {
                ulonglong2 av = ar[q];
                acc[2*q  ][0] = ffma2(av.x, w0,  acc[2*q  ][0]);
                acc[2*q  ][1] = ffma2(av.x, w1d, acc[2*q  ][1]);
                acc[2*q+1][0] = ffma2(av.y, w0,  acc[2*q+1][0]);
                acc[2*q+1][1] = ffma2(av.y, w1d, acc[2*q+1][1]);
            }
        }
    }
#pragma unroll
    for (int i = 0; i < 10; i++) {
        float2 wv = __ldg((const float2*)(B2 + i*OD + c0));
        ull w0 = pack2(wv.x, wv.x);
        ull w1d = pack2(wv.y, wv.y);
        const ulonglong2* ar = (const ulonglong2*)(a_sh + (640 + i)*16);
#pragma unroll
        for (int q = 0; q < 4; q++) {
            ulonglong2 av = ar[q];
            acc[2*q  ][0] = ffma2(av.x, w0,  acc[2*q  ][0]);
            acc[2*q  ][1] = ffma2(av.x, w1d, acc[2*q  ][1]);
            acc[2*q+1][0] = ffma2(av.y, w0,  acc[2*q+1][0]);
            acc[2*q+1][1] = ffma2(av.y, w1d, acc[2*q+1][1]);
        }
    }

    float* outp = ENEMY ? g_EmbEn : g_EmbAlSum;
#pragma unroll
    for (int p = 0; p < 8; p++) {
        float2 f0 = unpack2(acc[p][0]);   // col c0:   agents 2p, 2p+1
        float2 f1 = unpack2(acc[p][1]);   // col c0+1: agents 2p, 2p+1
        *(ull*)&outp[(ag0 + 2*p    )*OD + c0] = pack2(f0.x, f1.x);
        *(ull*)&outp[(ag0 + 2*p + 1)*OD + c0] = pack2(f0.y, f1.y);
    }
}

// ---------------------------------------------------------------------------
// Ally passing path: per-row GEMM against W2p (= pre-relu layer-1 activations),
// then relu(+pb1), @pw2, mean over heads, max over allies.
__global__ void __launch_bounds__(128) ally_pass_kernel(
    const float* __restrict__ feats,
    const float* __restrict__ W1, const float* __restrict__ B1,
    const float* __restrict__ pb1, const float* __restrict__ pw2,
    const float* __restrict__ pb2)
{
    __shared__ __align__(16) float a_sh[KK*16];   // reused as t_sh in epilogue
    __shared__ __align__(16) float h_sh[HH*16];   // reused as p_sh in epilogue
    __shared__ __align__(16) float e_sh[16*FD];
    const int tid = threadIdx.x;
    const int r0 = blockIdx.x;
    const int rowbase = r0 * NALLY;

    for (int idx = tid; idx < 16*FD; idx += 128) {
        float v = 0.f;
        if (idx < NALLY*FD) v = feats[rowbase*FD + idx];
        e_sh[idx] = v;
    }
    __syncthreads();

#pragma unroll
    for (int p = 0; p < 8; p++) {
        int idx = tid + p*128;
        int rr = idx & 15, k = idx >> 4;
        float s = 0.f;
        if (rr < NALLY) {
            s = B1[k];
#pragma unroll
            for (int i = 0; i < FD; i++) s = fmaf(e_sh[rr*FD + i], __ldg(W1 + i*HH + k), s);
            s = fmaxf(s, 0.f);
        }
        h_sh[idx] = s;
    }
    __syncthreads();

    for (int idx = tid; idx < KK*16; idx += 128) {
        int kk = idx >> 4, rr = idx & 15;
        float v;
        if (kk < 640) {
            int k = kk / 10, i = kk - k*10;
            v = h_sh[k*16 + rr] * e_sh[rr*FD + i];
        } else {
            v = e_sh[rr*FD + (kk - 640)];
        }
        a_sh[idx] = v;
    }
    __syncthreads();

    const int c0 = tid * 2;
    ull acc[8][2];
#pragma unroll
    for (int p = 0; p < 8; p++) { acc[p][0] = 0ull; acc[p][1] = 0ull; }

#pragma unroll 10
    for (int kk = 0; kk < KK; kk++) {
        float2 wv = __ldg((const float2*)(g_W2p + kk*OD + c0));
        ull w0 = pack2(wv.x, wv.x);
        ull w1d = pack2(wv.y, wv.y);
        const ulonglong2* ar = (const ulonglong2*)(a_sh + kk*16);
#pragma unroll
        for (int q = 0; q < 4; q++) {
            ulonglong2 av = ar[q];
            acc[2*q  ][0] = ffma2(av.x, w0,  acc[2*q  ][0]);
            acc[2*q  ][1] = ffma2(av.x, w1d, acc[2*q  ][1]);
            acc[2*q+1][0] = ffma2(av.y, w0,  acc[2*q+1][0]);
            acc[2*q+1][1] = ffma2(av.y, w1d, acc[2*q+1][1]);
        }
    }

    // epilogue: t = relu(z + pb1[j]); t_sh[col*20 + row]
    __syncthreads();
    float* t_sh = a_sh;
    const float bb0 = pb1[c0 & 63];
    const float bb1 = pb1[(c0 + 1) & 63];
#pragma unroll
    for (int p = 0; p < 8; p++) {
        float2 f0 = unpack2(acc[p][0]);
        float2 f1 = unpack2(acc[p][1]);
        *(ull*)(t_sh + c0*20 + 2*p)       = pack2(fmaxf(f0.x + bb0, 0.f), fmaxf(f0.y + bb0, 0.f));
        *(ull*)(t_sh + (c0+1)*20 + 2*p)   = pack2(fmaxf(f1.x + bb1, 0.f), fmaxf(f1.y + bb1, 0.f));
    }
    __syncthreads();

    // layer 2: p[row,hd,c] = sum_m t[row, hd*64+m] * pw2[m*3+c]; 96 threads
    float* p_sh = h_sh;   // 12*16 floats
    if (tid < 96) {
        int hd = tid / 24, rem = tid - hd*24, cc = rem >> 3, rp = rem & 7;
        ull ap = 0ull;
#pragma unroll 8
        for (int m = 0; m < 64; m++) {
            float wv = __ldg(pw2 + m*3 + cc);
            ull wd = pack2(wv, wv);
            ull tv = *(const ull*)(t_sh + (hd*64 + m)*20 + 2*rp);
            ap = ffma2(tv, wd, ap);
        }
        float2 f = unpack2(ap);
        p_sh[(hd*3 + cc)*16 + 2*rp]     = f.x;
        p_sh[(hd*3 + cc)*16 + 2*rp + 1] = f.y;
    }
    __syncthreads();

    if (tid < 3) {
        float mx = -INFINITY;
        float bb = pb2[tid];
        for (int row = 0; row < NALLY; row++) {
            float v = 0.25f * (p_sh[(0*3 + tid)*16 + row] + p_sh[(1*3 + tid)*16 + row] +
                               p_sh[(2*3 + tid)*16 + row] + p_sh[(3*3 + tid)*16 + row]) + bb;
            mx = fmaxf(mx, v);
        }
        g_PassEmb[r0*3 + tid] = mx;
    }
}

// ---------------------------------------------------------------------------
// Final: own-embed + merger softmax + GRU + fc2 + concat outputs
__global__ void __launch_bounds__(64) final_kernel(
    const float* __restrict__ own,
    const float* __restrict__ fc1_w, const float* __restrict__ fc1_b,
    const float* __restrict__ merger_w,
    const float* __restrict__ hstate,
    const float* __restrict__ wih, const float* __restrict__ whh,
    const float* __restrict__ bih, const float* __restrict__ bhh,
    const float* __restrict__ fc2_w1, const float* __restrict__ fc2_b1,
    const float* __restrict__ fc2_w2, const float* __restrict__ fc2_b2,
    float* __restrict__ out_q, float* __restrict__ out_h) {
    __shared__ float own_sh[32];
    __shared__ float x_sh[64];
    __shared__ float h_sh[64];
    __shared__ float hh_sh[64];
    __shared__ float t_sh[64];
    const int r = blockIdx.x;
    const int j = threadIdx.x;   // 64 threads
    if (j < 30) own_sh[j] = own[r*30 + j];
    h_sh[j] = hstate[r*64 + j];
    __syncthreads();

    float eo = fc1_b[j];
#pragma unroll
    for (int i = 0; i < 30; i++) eo = fmaf(own_sh[i], fc1_w[i*64 + j], eo);

    float w0 = merger_w[j], w1v = merger_w[64+j], w2v = merger_w[128+j], w3v = merger_w[192+j];
    float mx = fmaxf(fmaxf(w0, w1v), fmaxf(w2v, w3v));
    float e0 = expf(w0-mx), e1 = expf(w1v-mx), e2 = expf(w2v-mx), e3 = expf(w3v-mx);
    float inv = 1.f / (e0+e1+e2+e3);
    const float* en = g_EmbEn + r*OD;
    const float* al = g_EmbAlSum + r*OD;
    float m = e0*inv*(en[j]      + al[j])
            + e1*inv*(en[64+j]   + al[64+j])
            + e2*inv*(en[128+j]  + al[128+j])
            + e3*inv*(en[192+j]  + al[192+j]);

    float x = fmaxf(eo + m, 0.f);
    x_sh[j] = x;
    __syncthreads();

    float gi[3], gh[3];
#pragma unroll
    for (int t = 0; t < 3; t++) {
        int g = t*64 + j;
        float si = bih[g], sh = bhh[g];
        const float* wi = wih + g*64;
        const float* wh = whh + g*64;
#pragma unroll 8
        for (int k = 0; k < 64; k++) {
            si = fmaf(x_sh[k], __ldg(wi + k), si);
            sh = fmaf(h_sh[k], __ldg(wh + k), sh);
        }
        gi[t] = si; gh[t] = sh;
    }
    float rg = 1.f/(1.f + expf(-(gi[0]+gh[0])));
    float zg = 1.f/(1.f + expf(-(gi[1]+gh[1])));
    float ng = tanhf(gi[2] + rg*gh[2]);
    float hh = (1.f - zg)*ng + zg*h_sh[j];
    hh_sh[j] = hh;
    out_h[r*64 + j] = hh;
    __syncthreads();

    float tt = fc2_b1[j];
#pragma unroll 8
    for (int k = 0; k < 64; k++) tt = fmaf(hh_sh[k], fc2_w1[k*64 + j], tt);
    t_sh[j] = fmaxf(tt, 0.f);
    __syncthreads();

    if (j < 19) {
        float q = fc2_b2[j];
        for (int mm = 0; mm < 64; mm++) q = fmaf(t_sh[mm], fc2_w2[mm*19 + j], q);
        int col = (j < 9) ? j : j + 3;
        out_q[r*22 + col] = q;
    }
    if (j < 3) out_q[r*22 + 9 + j] = g_PassEmb[r*3 + j];
}

extern "C" void kernel_launch(void* const* d_in, const int* in_sizes, int n_in,
                              void* d_out, int out_size) {
    const float* own    = (const float*)d_in[1];
    const float* ally   = (const float*)d_in[2];
    const float* enemy  = (const float*)d_in[3];
    const float* hstate = (const float*)d_in[4];
    const float* fc1_w  = (const float*)d_in[5];
    const float* fc1_b  = (const float*)d_in[6];
    const float* he_w1  = (const float*)d_in[7];
    const float* he_b1  = (const float*)d_in[8];
    const float* he_w2  = (const float*)d_in[9];
    const float* he_b2  = (const float*)d_in[10];
    const float* ha_w1  = (const float*)d_in[11];
    const float* ha_b1  = (const float*)d_in[12];
    const float* ha_w2  = (const float*)d_in[13];
    const float* ha_b2  = (const float*)d_in[14];
    const float* merger = (const float*)d_in[15];
    const float* wih    = (const float*)d_in[16];
    const float* whh    = (const float*)d_in[17];
    const float* bih    = (const float*)d_in[18];
    const float* bhh    = (const float*)d_in[19];
    const float* fc2_w1 = (const float*)d_in[20];
    const float* fc2_b1 = (const float*)d_in[21];
    const float* fc2_w2 = (const float*)d_in[22];
    const float* fc2_b2 = (const float*)d_in[23];
    const float* pw1    = (const float*)d_in[24];
    const float* pb1    = (const float*)d_in[25];
    const float* pw2    = (const float*)d_in[26];
    const float* pb2    = (const float*)d_in[27];

    float* out   = (float*)d_out;
    float* out_q = out;              // [2048, 22]
    float* out_h = out + RR*22;      // [2048, 64]

    w2p_kernel<<<KK, 256>>>(ha_w2, ha_b2, pw1);
    summed_kernel<NEN,   true ><<<RR/16, 128>>>(enemy, he_w1, he_b1, he_w2, he_b2, 2820);
    summed_kernel<NALLY, false><<<RR/16, 128>>>(ally,  ha_w1, ha_b1, ha_w2, ha_b2, 2560);
    ally_pass_kernel<<<RR, 128>>>(ally, ha_w1, ha_b1, pb1, pw2, pb2);
    final_kernel<<<RR, 64>>>(own, fc1_w, fc1_b, merger, hstate,
                             wih, whh, bih, bhh,
                             fc2_w1, fc2_b1, fc2_w2, fc2_b2,
                             out_q, out_h);
}